// round 16
// baseline (speedup 1.0000x reference)
#include <cuda_runtime.h>
#include <cuda_fp16.h>
#include <cstdint>
#include <cstddef>

// ============================================================================
// GraphKANLayer on GB300 — fp16 tensor path, split-K x4, fused fp32->fp16
// A-conversion. R16 deltas vs R14/R15 (148.2us best):
//   * gemm: KSPLIT 2 -> 4 (KPC 32, grid 512) to fix 2-CTA/SM wave imbalance
//   * prep1: JT 16 -> 8 (smem ~25.6KB), max smem carveout, grid 1024
//   * reduce: 4-way partial sum
// Baseline PTX ISA only (compute_103 target rejects tcgen05).
// ============================================================================

#define FEAT 64
#define ODIM 64
#define NODES 8192
#define BATCH 4
#define NCOLS 256
#define INV_SQRT2F 0.70710678118654752440f
#define ADJ_SCALE 8192.0f
#define OUT_SCALE (1.0f / 8192.0f)

#define MT 128
#define NT 128
#define KCH 64                        // halfs per chunk (128B fp16 rows)
#define KSPLIT 4
#define KPC 32                        // chunks per CTA (K=2048)
#define A_BYTES (MT * KCH * 2)        // 16384 (fp16 A half of stage)
#define STAGE_BYTES (2 * A_BYTES)     // 32768 (A+B)
#define NSTG 3
#define SMEM_DYN (NSTG * STAGE_BYTES) // 98304 -> 2 CTAs/SM

#define JT 8                          // prep1 j-tile
#define W2S 68                        // w2s row stride (16B-aligned padding)

// ---- scratch (static device globals; cudaMalloc forbidden) ----
__device__ __align__(16) __half g_Yt_h[(size_t)NCOLS * NODES];         // 4 MB
__device__ __align__(16) float  g_part[KSPLIT][(size_t)NCOLS * NODES]; // 32 MB
__device__ float g_c[ODIM];

// ---------------------------------------------------------------------------
// PTX helpers (baseline ISA)
// ---------------------------------------------------------------------------
static __device__ __forceinline__ uint32_t smem_u32(const void* p) {
    uint32_t a;
    asm("{ .reg .u64 t; cvta.to.shared.u64 t, %1; cvt.u32.u64 %0, t; }"
        : "=r"(a) : "l"(p));
    return a;
}

static __device__ __forceinline__ void cp_async16(uint32_t dst, const void* src) {
    asm volatile("cp.async.cg.shared.global [%0], [%1], 16;"
                 :: "r"(dst), "l"(src) : "memory");
}
static __device__ __forceinline__ void cp_commit() {
    asm volatile("cp.async.commit_group;" ::: "memory");
}
template <int N>
static __device__ __forceinline__ void cp_wait() {
    asm volatile("cp.async.wait_group %0;" :: "n"(N) : "memory");
}

static __device__ __forceinline__ void ldsm_x4(uint32_t& r0, uint32_t& r1,
                                               uint32_t& r2, uint32_t& r3,
                                               uint32_t addr) {
    asm volatile("ldmatrix.sync.aligned.m8n8.x4.shared.b16 {%0,%1,%2,%3}, [%4];"
                 : "=r"(r0), "=r"(r1), "=r"(r2), "=r"(r3) : "r"(addr));
}

static __device__ __forceinline__ void mma_f16(float* d, const uint32_t* a,
                                               const uint32_t* b) {
    asm volatile(
        "mma.sync.aligned.m16n8k16.row.col.f32.f16.f16.f32 "
        "{%0,%1,%2,%3}, {%4,%5,%6,%7}, {%8,%9}, {%0,%1,%2,%3};"
        : "+f"(d[0]), "+f"(d[1]), "+f"(d[2]), "+f"(d[3])
        : "r"(a[0]), "r"(a[1]), "r"(a[2]), "r"(a[3]), "r"(b[0]), "r"(b[1]));
}

static __device__ __forceinline__ void sts64(uint32_t addr, uint32_t lo, uint32_t hi) {
    asm volatile("st.shared.v2.b32 [%0], {%1,%2};"
                 :: "r"(addr), "r"(lo), "r"(hi) : "memory");
}

static __device__ __forceinline__ uint32_t swz(uint32_t off) {
    return off ^ ((off >> 3) & 0x70);
}

static __device__ __forceinline__ uint32_t h2_as_u32(__half2 h) {
    union { __half2 h2; uint32_t u; } c;
    c.h2 = h;
    return c.u;
}

// ---------------------------------------------------------------------------
// prep1: Yt_h[b*64+o][j] = fp16( sum_f x[b,j,f] * W2[o,f] ); block 0 also
// computes c[o]. JT=8, smem ~25.6KB for >=3 resident blocks/SM.
// ---------------------------------------------------------------------------
__global__ void __launch_bounds__(256) prep1_kernel(const float* __restrict__ x,
                                                    const float* __restrict__ nl_w,
                                                    const float* __restrict__ nl_b,
                                                    const float* __restrict__ w_out,
                                                    const float* __restrict__ b_out) {
    __shared__ __align__(16) float xs[BATCH][JT][FEAT];   // 8 KB
    __shared__ __align__(16) float w2s[ODIM * W2S];       // 17.4 KB
    const int tid = threadIdx.x;
    const int j0 = blockIdx.x * JT;

    if (blockIdx.x == 0 && tid >= 64 && tid < 128) {
        int o = tid - 64;
        float a = b_out[o];
#pragma unroll 8
        for (int f = 0; f < FEAT; f++) a += nl_b[f] * w_out[o * FEAT + f];
        g_c[o] = a;
    }

    for (int i = tid; i < ODIM * FEAT; i += 256) {
        int o = i >> 6, f = i & 63;
        w2s[o * W2S + f] = INV_SQRT2F * nl_w[f] * w_out[i];
    }

#pragma unroll
    for (int i4 = tid; i4 < BATCH * JT * (FEAT / 4); i4 += 256) {  // 2 per thread
        int b = i4 >> 7;            // 128 float4 per batch (JT=8)
        int r = i4 & 127;
        int j = r >> 4;
        int f4 = r & 15;
        ((float4*)&xs[b][j][0])[f4] =
            ((const float4*)(x + ((size_t)b * NODES + j0 + j) * FEAT))[f4];
    }
    __syncthreads();

    const int o = tid & 63;
    const int b = tid >> 6;

    float accj[JT];
#pragma unroll
    for (int j = 0; j < JT; j++) accj[j] = 0.f;

#pragma unroll
    for (int fb = 0; fb < 4; fb++) {              // 16-wide f blocks
        float w2r[16];
#pragma unroll
        for (int q = 0; q < 4; q++)
            *(float4*)&w2r[q * 4] = *(const float4*)&w2s[o * W2S + fb * 16 + q * 4];
#pragma unroll
        for (int j = 0; j < JT; j++) {
            float a = accj[j];
#pragma unroll
            for (int q = 0; q < 4; q++) {
                float4 xv = ((const float4*)&xs[b][j][fb * 16])[q];  // broadcast
                a += xv.x * w2r[q * 4 + 0];
                a += xv.y * w2r[q * 4 + 1];
                a += xv.z * w2r[q * 4 + 2];
                a += xv.w * w2r[q * 4 + 3];
            }
            accj[j] = a;
        }
    }

    union { __half h[JT]; uint4 u; } ov;
#pragma unroll
    for (int j = 0; j < JT; j++) ov.h[j] = __float2half_rn(accj[j]);

    *(uint4*)(g_Yt_h + (size_t)(b * ODIM + o) * NODES + j0) = ov.u;
}

// ---------------------------------------------------------------------------
// Fused split-K GEMM: part[ks] = fp16(adj*2^13)[Kslice] @ Yt_h[Kslice]^T
// grid 512 = (n 2) x (ks 4) x (m 64); bit0 = n so adjacent CTAs share the
// fp32 A rows in L2. block 256 (8 warps: 2m x 4n, 64x32 each)
// ---------------------------------------------------------------------------
__global__ void __launch_bounds__(256, 2)
gemm_kernel(const float* __restrict__ adj) {
    extern __shared__ char dynsmem[];

    const int tid = threadIdx.x;
    const int wid = tid >> 5;
    const int lane = tid & 31;
    const int n0 = (blockIdx.x & 1) * NT;
    const int ks = (blockIdx.x >> 1) & 3;
    const int m0 = (blockIdx.x >> 3) * MT;
    const int k0 = ks * (NODES / KSPLIT);     // 2048-wide K slice
    const int wm = wid >> 2;     // 0..1  (m band of 64)
    const int wn = wid & 3;      // 0..3  (n band of 32)

    const uint32_t smem0 = smem_u32(dynsmem);

    // ---- A producer (fp32 LDG, coalesced): fseg = tid&15, r0 = tid>>4 ----
    const int fseg = tid & 15;
    const int r0 = tid >> 4;
    const float* aptr = adj + (size_t)(m0 + r0) * NODES + k0 + fseg * 4;
    const uint32_t abase = (uint32_t)(r0 * 128 + (((fseg >> 1) ^ (r0 & 7)) * 16)
                                      + (fseg & 1) * 8);

    // ---- B producer (cp.async): rb0 = tid>>3, sg = tid&7 ----
    const int rb0 = tid >> 3;
    const int sg = tid & 7;
    const uint32_t bbase = (uint32_t)A_BYTES +
        (uint32_t)(rb0 * 128 + ((sg ^ (rb0 & 7)) * 16));
    const __half* bptr = g_Yt_h + (size_t)(n0 + rb0) * NODES + k0 + sg * 8;

    // ---- consumer fragment offsets (pre-swizzled) — proven R8..R15 ----
    uint32_t pa[4];
    {
        int r15 = lane & 15;
        int h = lane >> 4;
#pragma unroll
        for (int mi = 0; mi < 4; mi++)
            pa[mi] = swz((uint32_t)((wm * 64 + mi * 16 + r15) * 128 + h * 16));
    }
    uint32_t pb[2];
    {
        int tile_sel = lane >> 4;
        int h = (lane >> 3) & 1;
        int rn = lane & 7;
#pragma unroll
        for (int nj = 0; nj < 2; nj++)
            pb[nj] = swz((uint32_t)((wn * 32 + (nj * 2 + tile_sel) * 8 + rn) * 128 + h * 16));
    }

    float acc[4][4][4];
#pragma unroll
    for (int mi = 0; mi < 4; mi++)
#pragma unroll
        for (int ni = 0; ni < 4; ni++)
#pragma unroll
            for (int q = 0; q < 4; q++) acc[mi][ni][q] = 0.f;

    auto ldgA = [&](int c, float4* av) {
#pragma unroll
        for (int t = 0; t < 8; t++)
            av[t] = *(const float4*)(aptr + (size_t)t * 16 * NODES + c * KCH);
    };
    auto stsA = [&](int c, const float4* av) {
        const uint32_t sb = smem0 + (uint32_t)(c % NSTG) * STAGE_BYTES;
#pragma unroll
        for (int t = 0; t < 8; t++) {
            float4 v = av[t];
            sts64(sb + abase + (uint32_t)t * 2048,
                  h2_as_u32(__floats2half2_rn(v.x * ADJ_SCALE, v.y * ADJ_SCALE)),
                  h2_as_u32(__floats2half2_rn(v.z * ADJ_SCALE, v.w * ADJ_SCALE)));
        }
    };
    auto loadB = [&](int c) {
        const uint32_t sb = smem0 + (uint32_t)(c % NSTG) * STAGE_BYTES;
#pragma unroll
        for (int t = 0; t < 4; t++)
            cp_async16(sb + bbase + (uint32_t)t * 4096,
                       bptr + (size_t)t * 32 * NODES + c * KCH);
    };

    // ---- prologue: chunks 0,1 fully staged ----
    {
        float4 av[8];
        ldgA(0, av); stsA(0, av);
        loadB(0); cp_commit();
        ldgA(1, av); stsA(1, av);
        loadB(1); cp_commit();
    }

    uint32_t fa[4][4];
    uint32_t fb[4][2];

    for (int i = 0; i < KPC; i++) {
        cp_wait<1>();            // B chunk i resident
        __syncthreads();         // readers of stage (i+2)%3 (iter i-1) passed

        const uint32_t sbase = smem0 + (uint32_t)(i % NSTG) * STAGE_BYTES;
        const int pc = i + 2;

        float4 av[8];
        if (pc < KPC) ldgA(pc, av);     // issue LDGs early (DRAM latency)
        if (pc < KPC) loadB(pc);
        cp_commit();                    // unconditional: fixed group count

        auto fetch = [&](int s) {
            const uint32_t xo = (uint32_t)s << 5;   // k16 step, XOR-safe
#pragma unroll
            for (int mi = 0; mi < 4; mi++)
                ldsm_x4(fa[mi][0], fa[mi][1], fa[mi][2], fa[mi][3],
                        sbase + (pa[mi] ^ xo));
#pragma unroll
            for (int nj = 0; nj < 2; nj++) {
                uint32_t r0_, r1_, r2_, r3_;
                ldsm_x4(r0_, r1_, r2_, r3_, sbase + A_BYTES + (pb[nj] ^ xo));
                fb[nj * 2 + 0][0] = r0_;
                fb[nj * 2 + 0][1] = r1_;
                fb[nj * 2 + 1][0] = r2_;
                fb[nj * 2 + 1][1] = r3_;
            }
        };

#pragma unroll
        for (int s = 0; s < 4; s++) {     // 4 k16 steps, single-buffered frags
            fetch(s);
#pragma unroll
            for (int mi = 0; mi < 4; mi++)
#pragma unroll
                for (int ni = 0; ni < 4; ni++)
                    mma_f16(acc[mi][ni], fa[mi], fb[ni]);
            if (s == 1 && pc < KPC) stsA(pc, av);  // cvt+STS mid-iteration
        }
        // no tail barrier: next head sync orders stage reuse
    }

    // ---- epilogue: raw partial sums to g_part[ks] ----
    const int qr = lane >> 2;
    const int qc = lane & 3;
    float* part = &g_part[ks][0];
#pragma unroll
    for (int mi = 0; mi < 4; mi++) {
        const int row0 = m0 + wm * 64 + mi * 16 + qr;
#pragma unroll
        for (int ni = 0; ni < 4; ni++) {
            const int ng = n0 + wn * 32 + ni * 8 + qc * 2;
            const int b = ng >> 6;
            const int o = ng & 63;
            float* d0 = part + ((size_t)b * NODES + row0) * ODIM + o;
            *(float2*)d0 = make_float2(acc[mi][ni][0], acc[mi][ni][1]);
            *(float2*)(d0 + 8 * ODIM) = make_float2(acc[mi][ni][2], acc[mi][ni][3]);
        }
    }
}

// ---------------------------------------------------------------------------
// reduce: out = (part0+part1+part2+part3) * 2^-13 + c[o]  (2 float4/thread)
// ---------------------------------------------------------------------------
__global__ void __launch_bounds__(256) reduce_kernel(float* __restrict__ out) {
    const size_t i8 = (size_t)blockIdx.x * 256 + threadIdx.x;
    const size_t e = i8 * 8;
#pragma unroll
    for (int h = 0; h < 2; h++) {
        const size_t eh = e + (size_t)h * 4;
        float4 p0 = *(const float4*)&g_part[0][eh];
        float4 p1 = *(const float4*)&g_part[1][eh];
        float4 p2 = *(const float4*)&g_part[2][eh];
        float4 p3 = *(const float4*)&g_part[3][eh];
        float4 c = *(const float4*)(g_c + (int)(eh & 63));
        float4 r;
        r.x = ((p0.x + p1.x) + (p2.x + p3.x)) * OUT_SCALE + c.x;
        r.y = ((p0.y + p1.y) + (p2.y + p3.y)) * OUT_SCALE + c.y;
        r.z = ((p0.z + p1.z) + (p2.z + p3.z)) * OUT_SCALE + c.z;
        r.w = ((p0.w + p1.w) + (p2.w + p3.w)) * OUT_SCALE + c.w;
        *(float4*)(out + eh) = r;
    }
}

// ---------------------------------------------------------------------------
// launch
// ---------------------------------------------------------------------------
extern "C" void kernel_launch(void* const* d_in, const int* in_sizes, int n_in,
                              void* d_out, int out_size) {
    (void)in_sizes; (void)n_in; (void)out_size;
    const float* x     = (const float*)d_in[0];
    const float* adj   = (const float*)d_in[1];
    const float* nl_w  = (const float*)d_in[2];
    const float* nl_b  = (const float*)d_in[3];
    const float* w_out = (const float*)d_in[4];
    const float* b_out = (const float*)d_in[5];
    float* out = (float*)d_out;

    cudaFuncSetAttribute(prep1_kernel,
                         cudaFuncAttributePreferredSharedMemoryCarveout, 100);
    prep1_kernel<<<NODES / JT, 256>>>(x, nl_w, nl_b, w_out, b_out);

    cudaFuncSetAttribute(gemm_kernel,
                         cudaFuncAttributeMaxDynamicSharedMemorySize, SMEM_DYN);
    gemm_kernel<<<512, 256, SMEM_DYN>>>(adj);

    reduce_kernel<<<(NCOLS * NODES) / (256 * 8), 256>>>(out);
}

// round 17
// speedup vs baseline: 1.1703x; 1.1703x over previous
#include <cuda_runtime.h>
#include <cuda_fp16.h>
#include <cstdint>
#include <cstddef>

// ============================================================================
// GraphKANLayer on GB300 — fp16 tensor path, fused fp32->fp16 A-conversion.
// R17: CTA tile 128x256 (full N), 64x64 warp tiles -> crossbar ~69% (was 100%),
// 1 CTA/SM, grid 128 = 64m x 2ks, single wave. Split-K back to 2.
// Baseline PTX ISA only (compute_103 target rejects tcgen05).
//
//   Yt_h[b*64+o, j] = fp16(sum_f x[b,j,f]*W2[o,f])  (prep1; also computes c[o])
//   part[ks] = fp16(adj*2^13)[:,Kslice] @ Yt_h[:,Kslice]^T   (GEMM, f32 acc)
//   out = (part0+part1) * 2^-13 + c[o]              (reduce, fused bias)
// ============================================================================

#define FEAT 64
#define ODIM 64
#define NODES 8192
#define BATCH 4
#define NCOLS 256
#define INV_SQRT2F 0.70710678118654752440f
#define ADJ_SCALE 8192.0f
#define OUT_SCALE (1.0f / 8192.0f)

#define MT 128
#define NT 256                        // full output width per CTA
#define KCH 64                        // halfs per chunk (128B fp16 rows)
#define KSPLIT 2
#define KPC 64                        // chunks per CTA (K=4096)
#define A_BYTES (MT * KCH * 2)        // 16384
#define B_BYTES (NT * KCH * 2)        // 32768
#define STAGE_BYTES (A_BYTES + B_BYTES)   // 49152
#define NSTG 3
#define SMEM_DYN (NSTG * STAGE_BYTES)     // 147456 (1 CTA/SM)

#define JT 16                         // prep1 j-tile
#define W2S 68                        // w2s row stride

// ---- scratch (static device globals; cudaMalloc forbidden) ----
__device__ __align__(16) __half g_Yt_h[(size_t)NCOLS * NODES];         // 4 MB
__device__ __align__(16) float  g_part[KSPLIT][(size_t)NCOLS * NODES]; // 16 MB
__device__ float g_c[ODIM];

// ---------------------------------------------------------------------------
// PTX helpers (baseline ISA)
// ---------------------------------------------------------------------------
static __device__ __forceinline__ uint32_t smem_u32(const void* p) {
    uint32_t a;
    asm("{ .reg .u64 t; cvta.to.shared.u64 t, %1; cvt.u32.u64 %0, t; }"
        : "=r"(a) : "l"(p));
    return a;
}

static __device__ __forceinline__ void cp_async16(uint32_t dst, const void* src) {
    asm volatile("cp.async.cg.shared.global [%0], [%1], 16;"
                 :: "r"(dst), "l"(src) : "memory");
}
static __device__ __forceinline__ void cp_commit() {
    asm volatile("cp.async.commit_group;" ::: "memory");
}
template <int N>
static __device__ __forceinline__ void cp_wait() {
    asm volatile("cp.async.wait_group %0;" :: "n"(N) : "memory");
}

static __device__ __forceinline__ void ldsm_x4(uint32_t& r0, uint32_t& r1,
                                               uint32_t& r2, uint32_t& r3,
                                               uint32_t addr) {
    asm volatile("ldmatrix.sync.aligned.m8n8.x4.shared.b16 {%0,%1,%2,%3}, [%4];"
                 : "=r"(r0), "=r"(r1), "=r"(r2), "=r"(r3) : "r"(addr));
}

static __device__ __forceinline__ void mma_f16(float* d, const uint32_t* a,
                                               const uint32_t* b) {
    asm volatile(
        "mma.sync.aligned.m16n8k16.row.col.f32.f16.f16.f32 "
        "{%0,%1,%2,%3}, {%4,%5,%6,%7}, {%8,%9}, {%0,%1,%2,%3};"
        : "+f"(d[0]), "+f"(d[1]), "+f"(d[2]), "+f"(d[3])
        : "r"(a[0]), "r"(a[1]), "r"(a[2]), "r"(a[3]), "r"(b[0]), "r"(b[1]));
}

static __device__ __forceinline__ void sts64(uint32_t addr, uint32_t lo, uint32_t hi) {
    asm volatile("st.shared.v2.b32 [%0], {%1,%2};"
                 :: "r"(addr), "r"(lo), "r"(hi) : "memory");
}

static __device__ __forceinline__ uint32_t swz(uint32_t off) {
    return off ^ ((off >> 3) & 0x70);
}

static __device__ __forceinline__ uint32_t h2_as_u32(__half2 h) {
    union { __half2 h2; uint32_t u; } c;
    c.h2 = h;
    return c.u;
}

// ---------------------------------------------------------------------------
// prep1: Yt_h[b*64+o][j] = fp16( sum_f x[b,j,f] * W2[o,f] ); block 0 also
// computes c[o].  (R14/R15-proven form, JT=16)
// ---------------------------------------------------------------------------
__global__ void __launch_bounds__(256) prep1_kernel(const float* __restrict__ x,
                                                    const float* __restrict__ nl_w,
                                                    const float* __restrict__ nl_b,
                                                    const float* __restrict__ w_out,
                                                    const float* __restrict__ b_out) {
    __shared__ __align__(16) float xs[BATCH][JT][FEAT];
    __shared__ __align__(16) float w2s[ODIM * W2S];
    const int tid = threadIdx.x;
    const int j0 = blockIdx.x * JT;

    if (blockIdx.x == 0 && tid >= 64 && tid < 128) {
        int o = tid - 64;
        float a = b_out[o];
#pragma unroll 8
        for (int f = 0; f < FEAT; f++) a += nl_b[f] * w_out[o * FEAT + f];
        g_c[o] = a;
    }

    for (int i = tid; i < ODIM * FEAT; i += 256) {
        int o = i >> 6, f = i & 63;
        w2s[o * W2S + f] = INV_SQRT2F * nl_w[f] * w_out[i];
    }

    for (int i4 = tid; i4 < BATCH * JT * (FEAT / 4); i4 += 256) {
        int b = i4 >> 8;
        int r = i4 & 255;
        int j = r >> 4;
        int f4 = r & 15;
        ((float4*)&xs[b][j][0])[f4] =
            ((const float4*)(x + ((size_t)b * NODES + j0 + j) * FEAT))[f4];
    }
    __syncthreads();

    const int o = tid & 63;
    const int b = tid >> 6;

    float accj[JT];
#pragma unroll
    for (int j = 0; j < JT; j++) accj[j] = 0.f;

#pragma unroll
    for (int fb = 0; fb < 4; fb++) {
        float w2r[16];
#pragma unroll
        for (int q = 0; q < 4; q++)
            *(float4*)&w2r[q * 4] = *(const float4*)&w2s[o * W2S + fb * 16 + q * 4];
#pragma unroll
        for (int j = 0; j < JT; j++) {
            float a = accj[j];
#pragma unroll
            for (int q = 0; q < 4; q++) {
                float4 xv = ((const float4*)&xs[b][j][fb * 16])[q];
                a += xv.x * w2r[q * 4 + 0];
                a += xv.y * w2r[q * 4 + 1];
                a += xv.z * w2r[q * 4 + 2];
                a += xv.w * w2r[q * 4 + 3];
            }
            accj[j] = a;
        }
    }

    union { __half h[JT]; uint4 u[2]; } ov;
#pragma unroll
    for (int j = 0; j < JT; j++) ov.h[j] = __float2half_rn(accj[j]);

    __half* dst = g_Yt_h + (size_t)(b * ODIM + o) * NODES + j0;
    ((uint4*)dst)[0] = ov.u[0];
    ((uint4*)dst)[1] = ov.u[1];
}

// ---------------------------------------------------------------------------
// Fused split-K GEMM, CTA tile 128x256, warp tile 64x64 (8 warps: 2m x 4n).
// grid 128 = (ks 2) x (m 64), 1 CTA/SM, single wave.
// ---------------------------------------------------------------------------
__global__ void __launch_bounds__(256, 1)
gemm_kernel(const float* __restrict__ adj) {
    extern __shared__ char dynsmem[];

    const int tid = threadIdx.x;
    const int wid = tid >> 5;
    const int lane = tid & 31;
    const int ks = blockIdx.x & 1;
    const int m0 = (blockIdx.x >> 1) * MT;
    const int k0 = ks * (NODES / KSPLIT);
    const int wm = wid >> 2;     // 0..1  (m band of 64)
    const int wn = wid & 3;      // 0..3  (n band of 64)

    const uint32_t smem0 = smem_u32(dynsmem);

    // ---- A producer (fp32 LDG, coalesced): fseg = tid&15, r0 = tid>>4 ----
    const int fseg = tid & 15;
    const int r0 = tid >> 4;
    const float* aptr = adj + (size_t)(m0 + r0) * NODES + k0 + fseg * 4;
    const uint32_t abase = (uint32_t)(r0 * 128 + (((fseg >> 1) ^ (r0 & 7)) * 16)
                                      + (fseg & 1) * 8);

    // ---- B producer (cp.async): rb0 = tid>>3 (rows rb0+32t, t=0..7) ----
    const int rb0 = tid >> 3;
    const int sg = tid & 7;
    const uint32_t bbase = (uint32_t)A_BYTES +
        (uint32_t)(rb0 * 128 + ((sg ^ (rb0 & 7)) * 16));
    const __half* bptr = g_Yt_h + (size_t)rb0 * NODES + k0 + sg * 8;

    // ---- consumer fragment offsets (pre-swizzled) ----
    uint32_t pa[4];
    {
        int r15 = lane & 15;
        int h = lane >> 4;
#pragma unroll
        for (int mi = 0; mi < 4; mi++)
            pa[mi] = swz((uint32_t)((wm * 64 + mi * 16 + r15) * 128 + h * 16));
    }
    uint32_t pb[4];                  // 4 ldsm.x4 per step -> 8 n8-tiles
    {
        int tile_sel = lane >> 4;
        int h = (lane >> 3) & 1;
        int rn = lane & 7;
#pragma unroll
        for (int nj = 0; nj < 4; nj++)
            pb[nj] = swz((uint32_t)((wn * 64 + (nj * 2 + tile_sel) * 8 + rn) * 128 + h * 16));
    }

    float acc[4][8][4];
#pragma unroll
    for (int mi = 0; mi < 4; mi++)
#pragma unroll
        for (int ni = 0; ni < 8; ni++)
#pragma unroll
            for (int q = 0; q < 4; q++) acc[mi][ni][q] = 0.f;

    auto ldgA = [&](int c, float4* av) {
#pragma unroll
        for (int t = 0; t < 8; t++)
            av[t] = *(const float4*)(aptr + (size_t)t * 16 * NODES + c * KCH);
    };
    auto stsA = [&](int c, const float4* av) {
        const uint32_t sb = smem0 + (uint32_t)(c % NSTG) * STAGE_BYTES;
#pragma unroll
        for (int t = 0; t < 8; t++) {
            float4 v = av[t];
            sts64(sb + abase + (uint32_t)t * 2048,
                  h2_as_u32(__floats2half2_rn(v.x * ADJ_SCALE, v.y * ADJ_SCALE)),
                  h2_as_u32(__floats2half2_rn(v.z * ADJ_SCALE, v.w * ADJ_SCALE)));
        }
    };
    auto loadB = [&](int c) {
        const uint32_t sb = smem0 + (uint32_t)(c % NSTG) * STAGE_BYTES;
#pragma unroll
        for (int t = 0; t < 8; t++)      // 8 x 16B: rows rb0+32t (0..255)
            cp_async16(sb + bbase + (uint32_t)t * 4096,
                       bptr + (size_t)t * 32 * NODES + c * KCH);
    };

    // ---- prologue: chunks 0,1 fully staged ----
    {
        float4 av[8];
        ldgA(0, av); stsA(0, av);
        loadB(0); cp_commit();
        ldgA(1, av); stsA(1, av);
        loadB(1); cp_commit();
    }

    uint32_t fa[4][4];
    uint32_t fb[8][2];

    for (int i = 0; i < KPC; i++) {
        cp_wait<1>();            // B chunk i resident
        __syncthreads();         // readers of stage (i+2)%3 (iter i-1) passed

        const uint32_t sbase = smem0 + (uint32_t)(i % NSTG) * STAGE_BYTES;
        const int pc = i + 2;

        float4 av[8];
        if (pc < KPC) ldgA(pc, av);     // issue LDGs early (DRAM latency)
        if (pc < KPC) loadB(pc);
        cp_commit();                    // unconditional: fixed group count

        auto fetch = [&](int s) {
            const uint32_t xo = (uint32_t)s << 5;   // k16 step, XOR-safe
#pragma unroll
            for (int mi = 0; mi < 4; mi++)
                ldsm_x4(fa[mi][0], fa[mi][1], fa[mi][2], fa[mi][3],
                        sbase + (pa[mi] ^ xo));
#pragma unroll
            for (int nj = 0; nj < 4; nj++) {
                uint32_t q0, q1, q2, q3;
                ldsm_x4(q0, q1, q2, q3, sbase + A_BYTES + (pb[nj] ^ xo));
                fb[nj * 2 + 0][0] = q0;
                fb[nj * 2 + 0][1] = q1;
                fb[nj * 2 + 1][0] = q2;
                fb[nj * 2 + 1][1] = q3;
            }
        };

#pragma unroll
        for (int s = 0; s < 4; s++) {     // 4 k16 steps
            fetch(s);
#pragma unroll
            for (int mi = 0; mi < 4; mi++)
#pragma unroll
                for (int ni = 0; ni < 8; ni++)
                    mma_f16(acc[mi][ni], fa[mi], fb[ni]);
            if (s == 1 && pc < KPC) stsA(pc, av);  // cvt+STS mid-iteration
        }
        // no tail barrier: next head sync orders stage reuse
    }

    // ---- epilogue: raw partial sums to g_part[ks] ----
    const int qr = lane >> 2;
    const int qc = lane & 3;
    float* part = &g_part[ks][0];
#pragma unroll
    for (int mi = 0; mi < 4; mi++) {
        const int row0 = m0 + wm * 64 + mi * 16 + qr;
#pragma unroll
        for (int ni = 0; ni < 8; ni++) {
            const int ng = wn * 64 + ni * 8 + qc * 2;
            const int b = ng >> 6;
            const int o = ng & 63;
            float* d0 = part + ((size_t)b * NODES + row0) * ODIM + o;
            *(float2*)d0 = make_float2(acc[mi][ni][0], acc[mi][ni][1]);
            *(float2*)(d0 + 8 * ODIM) = make_float2(acc[mi][ni][2], acc[mi][ni][3]);
        }
    }
}

// ---------------------------------------------------------------------------
// reduce: out = (part0 + part1) * 2^-13 + c[o]   (2 float4 per thread)
// ---------------------------------------------------------------------------
__global__ void __launch_bounds__(256) reduce_kernel(float* __restrict__ out) {
    const size_t i8 = (size_t)blockIdx.x * 256 + threadIdx.x;
    const size_t e = i8 * 8;
#pragma unroll
    for (int h = 0; h < 2; h++) {
        const size_t eh = e + (size_t)h * 4;
        float4 p0 = *(const float4*)&g_part[0][eh];
        float4 p1 = *(const float4*)&g_part[1][eh];
        float4 c = *(const float4*)(g_c + (int)(eh & 63));
        float4 r;
        r.x = (p0.x + p1.x) * OUT_SCALE + c.x;
        r.y = (p0.y + p1.y) * OUT_SCALE + c.y;
        r.z = (p0.z + p1.z) * OUT_SCALE + c.z;
        r.w = (p0.w + p1.w) * OUT_SCALE + c.w;
        *(float4*)(out + eh) = r;
    }
}

// ---------------------------------------------------------------------------
// launch
// ---------------------------------------------------------------------------
extern "C" void kernel_launch(void* const* d_in, const int* in_sizes, int n_in,
                              void* d_out, int out_size) {
    (void)in_sizes; (void)n_in; (void)out_size;
    const float* x     = (const float*)d_in[0];
    const float* adj   = (const float*)d_in[1];
    const float* nl_w  = (const float*)d_in[2];
    const float* nl_b  = (const float*)d_in[3];
    const float* w_out = (const float*)d_in[4];
    const float* b_out = (const float*)d_in[5];
    float* out = (float*)d_out;

    prep1_kernel<<<NODES / JT, 256>>>(x, nl_w, nl_b, w_out, b_out);

    cudaFuncSetAttribute(gemm_kernel,
                         cudaFuncAttributeMaxDynamicSharedMemorySize, SMEM_DYN);
    gemm_kernel<<<128, 256, SMEM_DYN>>>(adj);

    reduce_kernel<<<(NCOLS * NODES) / (256 * 8), 256>>>(out);
}